// round 6
// baseline (speedup 1.0000x reference)
#include <cuda_runtime.h>
#include <math.h>

// Problem constants (fixed shapes per reference)
#define NN 100000
#define BB 1024
#define LAT 128
#define INDIM 384      // NODE_DIM + 2*LATENT
#define FFNIN 512      // LATENT + IN_DIM
#define CAP 512        // neighbor list capacity (mean ~50)
#define GQ 8           // queries per block in prep/epi

// Scratch (device globals; no allocation allowed)
__device__ float g_qin[BB * INDIM];
__device__ float g_qk[BB * INDIM];
__device__ float g_qbias[BB];
__device__ float g_acc[BB * INDIM];
__device__ int   g_list[BB * CAP];
__device__ int   g_cnt[BB];

// Merge two partial-sum arrays across xor-lane distance `bit`
__device__ __forceinline__ float mrg(float a, float b, int bit, int lane) {
    float keep = (lane & bit) ? b : a;
    float send = (lane & bit) ? a : b;
    return keep + __shfl_xor_sync(0xffffffffu, send, bit);
}

// ---------------------------------------------------------------------------
// Kernel 1: prep. 128 blocks x 512 threads (side stream, hidden under scan).
// ---------------------------------------------------------------------------
__global__ void __launch_bounds__(512) k_prep(
    const float* __restrict__ x, const float* __restrict__ mem,
    const float* __restrict__ tart, const int* __restrict__ tidx,
    const float* __restrict__ Wq, const float* __restrict__ bq,
    const float* __restrict__ Wk, const float* __restrict__ bk)
{
    int b0 = blockIdx.x * GQ;
    int t = threadIdx.x, lane = t & 31, w = t >> 5;
    __shared__ float qin[GQ][INDIM];
    __shared__ float qsm[GQ][LAT];
    __shared__ float wk_sm[16][INDIM];
    __shared__ int sidx[GQ];

    if (t < GQ) sidx[t] = tidx[b0 + t];
    __syncthreads();

    for (int m = t; m < GQ * 96; m += 512) {
        int q = m / 96, c4 = m % 96;
        float4 v;
        if (c4 < 32)      v = ((const float4*)(x    + (size_t)sidx[q] * LAT))[c4];
        else if (c4 < 64) v = ((const float4*)(mem  + (size_t)sidx[q] * LAT))[c4 - 32];
        else              v = ((const float4*)(tart + (size_t)(b0 + q) * LAT))[c4 - 64];
        *(float4*)&qin[q][c4 * 4] = v;
        *(float4*)&g_qin[(size_t)(b0 + q) * INDIM + c4 * 4] = v;
    }
    __syncthreads();

    // q = Wq @ qin + bq  (warp-per-output, multi-reduce)
    for (int oi = 0; oi < 8; oi++) {
        int o = (w & 15) * 8 + oi;
        const float* wr = Wq + (size_t)o * INDIM;
        float wreg[12];
        #pragma unroll
        for (int r = 0; r < 12; r++) wreg[r] = wr[lane + 32 * r];
        float p[GQ];
        #pragma unroll
        for (int q = 0; q < GQ; q++) {
            float s = 0.f;
            #pragma unroll
            for (int r = 0; r < 12; r++) s = fmaf(wreg[r], qin[q][lane + 32 * r], s);
            p[q] = s;
        }
        float a0 = mrg(p[0], p[1], 16, lane), a1 = mrg(p[2], p[3], 16, lane);
        float a2 = mrg(p[4], p[5], 16, lane), a3 = mrg(p[6], p[7], 16, lane);
        float b4 = mrg(a0, a1, 8, lane), b5 = mrg(a2, a3, 8, lane);
        float c0 = mrg(b4, b5, 4, lane);
        c0 += __shfl_xor_sync(0xffffffffu, c0, 1);
        c0 += __shfl_xor_sync(0xffffffffu, c0, 2);
        float bias = bq[o];
        if ((lane & 3) == 0) {
            int q = ((lane >> 4) & 1) + ((lane >> 2) & 2) + (lane & 4);
            qsm[q][o] = c0 + bias;
        }
    }
    __syncthreads();

    // qbias[q] = q . bk
    if (w < GQ) {
        float v = 0.f;
        #pragma unroll
        for (int r = 0; r < 4; r++) v = fmaf(qsm[w][lane + 32 * r], bk[lane + 32 * r], v);
        #pragma unroll
        for (int off = 16; off; off >>= 1) v += __shfl_xor_sync(0xffffffffu, v, off);
        if (lane == 0) g_qbias[b0 + w] = v;
    }

    // qk = Wk^T q  (smem-staged Wk tiles)
    float acc[GQ];
    #pragma unroll
    for (int q = 0; q < GQ; q++) acc[q] = 0.f;
    for (int j0 = 0; j0 < LAT; j0 += 16) {
        __syncthreads();
        for (int m = t; m < 16 * 96; m += 512) {
            int jj = m / 96, c4 = m % 96;
            *(float4*)&wk_sm[jj][c4 * 4] =
                ((const float4*)(Wk + (size_t)(j0 + jj) * INDIM))[c4];
        }
        __syncthreads();
        if (t < INDIM) {
            #pragma unroll
            for (int jj = 0; jj < 16; jj++) {
                float wv = wk_sm[jj][t];
                #pragma unroll
                for (int q = 0; q < GQ; q++) acc[q] = fmaf(qsm[q][j0 + jj], wv, acc[q]);
            }
        }
    }
    if (t < INDIM) {
        #pragma unroll
        for (int q = 0; q < GQ; q++) g_qk[(size_t)(b0 + q) * INDIM + t] = acc[q];
    }
}

// ---------------------------------------------------------------------------
// Kernel 2: mask scan -> edge lists. 1024 blocks x 256 thr.
// Mask is PROVEN 4-byte elements (R3/R5 traffic = 413MB): word != 0 <=> edge.
// Streaming loads (__ldcs): mask is read-once, evict-first.
// ---------------------------------------------------------------------------
#define PROC4(u, base) \
    if (u.x | u.y | u.z | u.w) { \
        if (u.x) { int sl = atomicAdd(&s_cnt, 1); if (sl < CAP) s_idx[sl] = (base) * 4 + 0; } \
        if (u.y) { int sl = atomicAdd(&s_cnt, 1); if (sl < CAP) s_idx[sl] = (base) * 4 + 1; } \
        if (u.z) { int sl = atomicAdd(&s_cnt, 1); if (sl < CAP) s_idx[sl] = (base) * 4 + 2; } \
        if (u.w) { int sl = atomicAdd(&s_cnt, 1); if (sl < CAP) s_idx[sl] = (base) * 4 + 3; } }

__global__ void __launch_bounds__(256) k_scan(
    const unsigned char* __restrict__ maskb, const int* __restrict__ tidx)
{
    int b = blockIdx.x, t = threadIdx.x;
    __shared__ int s_idx[CAP];
    __shared__ int s_cnt;
    if (t == 0) s_cnt = 0;
    __syncthreads();

    const uint4* row = (const uint4*)(maskb + (size_t)b * NN * 4);
    const int NW = NN / 4;                    // 25000 uint4
    int i = t;
    for (; i + 768 < NW; i += 1024) {
        uint4 a  = __ldcs(row + i);
        uint4 b4 = __ldcs(row + i + 256);
        uint4 c4 = __ldcs(row + i + 512);
        uint4 d4 = __ldcs(row + i + 768);
        PROC4(a, i) PROC4(b4, i + 256) PROC4(c4, i + 512) PROC4(d4, i + 768)
    }
    for (; i < NW; i += 256) { uint4 u = __ldcs(row + i); PROC4(u, i) }

    __syncthreads();
    int cnt = min(s_cnt, CAP);
    if (cnt == 0) {
        if (t == 0) { g_list[b * CAP] = tidx[b]; g_cnt[b] = 1; }
        return;
    }
    for (int m = t; m < cnt; m += 256) g_list[b * CAP + m] = s_idx[m];
    if (t == 0) g_cnt[b] = cnt;
}

// ---------------------------------------------------------------------------
// Kernel 3: online-softmax gather. 1024 blocks x 1024 thr (32 warps).
// Each warp owns ~1-2 edges -> at most ~2 exposed DRAM latencies.
// ---------------------------------------------------------------------------
__global__ void __launch_bounds__(1024) k_gather(
    const float* __restrict__ x, const float* __restrict__ mem,
    const float* __restrict__ dt)
{
    int b = blockIdx.x, t = threadIdx.x, lane = t & 31, w = t >> 5;
    __shared__ float s_qk[INDIM];
    __shared__ float s_part[32][INDIM];
    __shared__ float s_m[32], s_l[32], s_ef[32];
    __shared__ float s_invL;

    if (t < INDIM) s_qk[t] = g_qk[(size_t)b * INDIM + t];
    __syncthreads();
    int cnt = g_cnt[b];
    float qb = g_qbias[b];
    const float scale = 0.08838834764831845f;   // 1/sqrt(128)

    float m = -INFINITY, l = 0.f;
    float racc[12];
    #pragma unroll
    for (int r = 0; r < 12; r++) racc[r] = 0.f;

    for (int p = w; p < cnt; p += 32) {
        int n = g_list[b * CAP + p];
        const float* px = x   + (size_t)n * LAT;
        const float* pm = mem + (size_t)n * LAT;
        const float* pd = dt  + (size_t)n * LAT;
        float rowv[12];
        #pragma unroll
        for (int r = 0; r < 4; r++) rowv[r]     = px[lane + 32 * r];
        #pragma unroll
        for (int r = 0; r < 4; r++) rowv[4 + r] = pm[lane + 32 * r];
        #pragma unroll
        for (int r = 0; r < 4; r++) rowv[8 + r] = pd[lane + 32 * r];
        float dot = 0.f;
        #pragma unroll
        for (int r = 0; r < 12; r++) dot = fmaf(rowv[r], s_qk[32 * r + lane], dot);
        #pragma unroll
        for (int off = 16; off; off >>= 1) dot += __shfl_xor_sync(0xffffffffu, dot, off);
        float s = (dot + qb) * scale;
        float mnew = fmaxf(m, s);
        float corr = __expf(m - mnew);
        float e = __expf(s - mnew);
        l = l * corr + e;
        m = mnew;
        #pragma unroll
        for (int r = 0; r < 12; r++) racc[r] = fmaf(racc[r], corr, e * rowv[r]);
    }
    #pragma unroll
    for (int r = 0; r < 12; r++) s_part[w][32 * r + lane] = racc[r];
    if (lane == 0) { s_m[w] = m; s_l[w] = l; }
    __syncthreads();

    // warp 0 merges the 32 online-softmax states
    if (w == 0) {
        float mi = s_m[lane];
        float M = mi;
        #pragma unroll
        for (int off = 16; off; off >>= 1) M = fmaxf(M, __shfl_xor_sync(0xffffffffu, M, off));
        float ef = __expf(mi - M);              // 0 for empty warps (mi = -inf)
        float Lc = s_l[lane] * ef;
        float L = Lc;
        #pragma unroll
        for (int off = 16; off; off >>= 1) L += __shfl_xor_sync(0xffffffffu, L, off);
        s_ef[lane] = ef;
        if (lane == 0) s_invL = 1.f / L;
    }
    __syncthreads();

    float invL = s_invL;
    if (t < INDIM) {
        float sum = 0.f;
        #pragma unroll
        for (int i = 0; i < 32; i++) sum = fmaf(s_part[i][t], s_ef[i], sum);
        g_acc[(size_t)b * INDIM + t] = sum * invL;
    }
}

// ---------------------------------------------------------------------------
// Kernel 4: epilogue. 128 blocks x 512 threads. Multi-reduce GEMV stages.
// ---------------------------------------------------------------------------
__global__ void __launch_bounds__(512) k_epi(
    const float* __restrict__ Wv, const float* __restrict__ bv,
    const float* __restrict__ W1, const float* __restrict__ b1,
    const float* __restrict__ W2, const float* __restrict__ b2,
    float* __restrict__ out)
{
    int b0 = blockIdx.x * GQ;
    int t = threadIdx.x, lane = t & 31, w = t >> 5;
    __shared__ float acc[GQ][INDIM];
    __shared__ float z[GQ][FFNIN];
    __shared__ float h[GQ][LAT];

    for (int m = t; m < GQ * 96; m += 512) {
        int q = m / 96, c4 = m % 96;
        *(float4*)&acc[q][c4 * 4]     = *(const float4*)&g_acc[(size_t)(b0 + q) * INDIM + c4 * 4];
        *(float4*)&z[q][LAT + c4 * 4] = *(const float4*)&g_qin[(size_t)(b0 + q) * INDIM + c4 * 4];
    }
    __syncthreads();

    // z[:, :128] = Wv @ acc + bv
    for (int oi = 0; oi < 8; oi++) {
        int o = w * 8 + oi;
        const float* wr = Wv + (size_t)o * INDIM;
        float wreg[12];
        #pragma unroll
        for (int r = 0; r < 12; r++) wreg[r] = wr[lane + 32 * r];
        float p[GQ];
        #pragma unroll
        for (int q = 0; q < GQ; q++) {
            float s = 0.f;
            #pragma unroll
            for (int r = 0; r < 12; r++) s = fmaf(wreg[r], acc[q][lane + 32 * r], s);
            p[q] = s;
        }
        float a0 = mrg(p[0], p[1], 16, lane), a1 = mrg(p[2], p[3], 16, lane);
        float a2 = mrg(p[4], p[5], 16, lane), a3 = mrg(p[6], p[7], 16, lane);
        float b4 = mrg(a0, a1, 8, lane), b5 = mrg(a2, a3, 8, lane);
        float c0 = mrg(b4, b5, 4, lane);
        c0 += __shfl_xor_sync(0xffffffffu, c0, 1);
        c0 += __shfl_xor_sync(0xffffffffu, c0, 2);
        float bias = bv[o];
        if ((lane & 3) == 0) {
            int q = ((lane >> 4) & 1) + ((lane >> 2) & 2) + (lane & 4);
            z[q][o] = c0 + bias;
        }
    }
    __syncthreads();

    // h = relu(W1 @ z + b1)
    for (int oi = 0; oi < 8; oi++) {
        int o = w * 8 + oi;
        const float* wr = W1 + (size_t)o * FFNIN;
        float wreg[16];
        #pragma unroll
        for (int r = 0; r < 16; r++) wreg[r] = wr[lane + 32 * r];
        float p[GQ];
        #pragma unroll
        for (int q = 0; q < GQ; q++) {
            float s = 0.f;
            #pragma unroll
            for (int r = 0; r < 16; r++) s = fmaf(wreg[r], z[q][lane + 32 * r], s);
            p[q] = s;
        }
        float a0 = mrg(p[0], p[1], 16, lane), a1 = mrg(p[2], p[3], 16, lane);
        float a2 = mrg(p[4], p[5], 16, lane), a3 = mrg(p[6], p[7], 16, lane);
        float b4 = mrg(a0, a1, 8, lane), b5 = mrg(a2, a3, 8, lane);
        float c0 = mrg(b4, b5, 4, lane);
        c0 += __shfl_xor_sync(0xffffffffu, c0, 1);
        c0 += __shfl_xor_sync(0xffffffffu, c0, 2);
        float bias = b1[o];
        if ((lane & 3) == 0) {
            int q = ((lane >> 4) & 1) + ((lane >> 2) & 2) + (lane & 4);
            h[q][o] = fmaxf(c0 + bias, 0.f);
        }
    }
    __syncthreads();

    // out = W2 @ h + b2
    for (int oi = 0; oi < 8; oi++) {
        int o = w * 8 + oi;
        const float* wr = W2 + (size_t)o * LAT;
        float wreg[4];
        #pragma unroll
        for (int r = 0; r < 4; r++) wreg[r] = wr[lane + 32 * r];
        float p[GQ];
        #pragma unroll
        for (int q = 0; q < GQ; q++) {
            float s = 0.f;
            #pragma unroll
            for (int r = 0; r < 4; r++) s = fmaf(wreg[r], h[q][lane + 32 * r], s);
            p[q] = s;
        }
        float a0 = mrg(p[0], p[1], 16, lane), a1 = mrg(p[2], p[3], 16, lane);
        float a2 = mrg(p[4], p[5], 16, lane), a3 = mrg(p[6], p[7], 16, lane);
        float b4 = mrg(a0, a1, 8, lane), b5 = mrg(a2, a3, 8, lane);
        float c0 = mrg(b4, b5, 4, lane);
        c0 += __shfl_xor_sync(0xffffffffu, c0, 1);
        c0 += __shfl_xor_sync(0xffffffffu, c0, 2);
        float bias = b2[o];
        if ((lane & 3) == 0) {
            int q = ((lane >> 4) & 1) + ((lane >> 2) & 2) + (lane & 4);
            out[(size_t)(b0 + q) * LAT + o] = c0 + bias;
        }
    }
}

// ---------------------------------------------------------------------------
extern "C" void kernel_launch(void* const* d_in, const int* in_sizes, int n_in,
                              void* d_out, int out_size)
{
    const float* x    = (const float*)d_in[0];
    const float* mem  = (const float*)d_in[1];
    const float* dt   = (const float*)d_in[2];
    const float* tart = (const float*)d_in[3];
    const unsigned char* mask = (const unsigned char*)d_in[4];
    const int*   tidx = (const int*)d_in[5];
    const float* Wq = (const float*)d_in[6];
    const float* bq = (const float*)d_in[7];
    const float* Wk = (const float*)d_in[8];
    const float* bk = (const float*)d_in[9];
    const float* Wv = (const float*)d_in[10];
    const float* bv = (const float*)d_in[11];
    const float* W1 = (const float*)d_in[12];
    const float* b1 = (const float*)d_in[13];
    const float* W2 = (const float*)d_in[14];
    const float* b2 = (const float*)d_in[15];
    float* out = (float*)d_out;

    // Fork-join: prep (weights path) runs concurrently with scan (mask path).
    static cudaStream_t s_side = nullptr;
    static cudaEvent_t e_fork = nullptr, e_join = nullptr;
    if (s_side == nullptr) {
        cudaStreamCreateWithFlags(&s_side, cudaStreamNonBlocking);
        cudaEventCreateWithFlags(&e_fork, cudaEventDisableTiming);
        cudaEventCreateWithFlags(&e_join, cudaEventDisableTiming);
    }

    cudaEventRecord(e_fork, 0);
    cudaStreamWaitEvent(s_side, e_fork, 0);
    k_prep<<<BB / GQ, 512, 0, s_side>>>(x, mem, tart, tidx, Wq, bq, Wk, bk);
    cudaEventRecord(e_join, s_side);

    k_scan<<<BB, 256>>>(mask, tidx);

    cudaStreamWaitEvent(0, e_join, 0);
    k_gather<<<BB, 1024>>>(x, mem, dt);
    k_epi<<<BB / GQ, 512>>>(Wv, bv, W1, b1, W2, b2, out);
}

// round 7
// speedup vs baseline: 1.1685x; 1.1685x over previous
#include <cuda_runtime.h>
#include <math.h>

// Problem constants (fixed shapes per reference)
#define NN 100000
#define BB 1024
#define LAT 128
#define INDIM 384      // NODE_DIM + 2*LATENT
#define FFNIN 512      // LATENT + IN_DIM
#define CAP 512        // neighbor list capacity (mean ~50)
#define GQ 8           // queries per block in prep/epi

// Scratch (device globals; no allocation allowed)
__device__ float g_qk[BB * INDIM];
__device__ float g_qbias[BB];
__device__ float g_acc[BB * INDIM];
__device__ float g_hpart[BB * LAT];     // W1b @ q_input + b1
__device__ float g_Wfold[LAT * INDIM];  // W1a @ Wv
__device__ float g_cvec[LAT];           // W1a @ bv
__device__ int   g_list[BB * CAP];
__device__ int   g_cnt[BB];

// Merge two partial-sum arrays across xor-lane distance `bit`
__device__ __forceinline__ float mrg(float a, float b, int bit, int lane) {
    float keep = (lane & bit) ? b : a;
    float send = (lane & bit) ? a : b;
    return keep + __shfl_xor_sync(0xffffffffu, send, bit);
}

// ---------------------------------------------------------------------------
// Kernel 0 (side stream): fold FFN layer-1 through Wv.
//   Wfold[o][c] = sum_j W1[o][j] * Wv[j][c]   (j < 128: W1a block)
//   cvec[o]    = sum_j W1[o][j] * bv[j]
// 128 blocks (one per output row o) x 384 threads.
// ---------------------------------------------------------------------------
__global__ void __launch_bounds__(384) k_fold(
    const float* __restrict__ W1, const float* __restrict__ Wv,
    const float* __restrict__ bv)
{
    int o = blockIdx.x, t = threadIdx.x;
    __shared__ float w1a[LAT];
    __shared__ float red[4];
    if (t < LAT) w1a[t] = W1[(size_t)o * FFNIN + t];
    __syncthreads();

    float s = 0.f;
    #pragma unroll 4
    for (int j = 0; j < LAT; j++) s = fmaf(w1a[j], Wv[(size_t)j * INDIM + t], s);
    g_Wfold[o * INDIM + t] = s;

    if (t < LAT) {
        float v = w1a[t] * bv[t];
        #pragma unroll
        for (int off = 16; off; off >>= 1) v += __shfl_xor_sync(0xffffffffu, v, off);
        if ((t & 31) == 0) red[t >> 5] = v;
    }
    __syncthreads();
    if (t == 0) g_cvec[o] = red[0] + red[1] + red[2] + red[3];
}

// ---------------------------------------------------------------------------
// Kernel 1 (side stream): prep. 128 blocks x 512 threads.
//   qin = [x[idx], mem[idx], tar_t]; q = Wq@qin + bq; qbias = q.bk
//   qk = Wk^T q ;  hpart = W1b@qin + b1
// ---------------------------------------------------------------------------
__global__ void __launch_bounds__(512) k_prep(
    const float* __restrict__ x, const float* __restrict__ mem,
    const float* __restrict__ tart, const int* __restrict__ tidx,
    const float* __restrict__ Wq, const float* __restrict__ bq,
    const float* __restrict__ Wk, const float* __restrict__ bk,
    const float* __restrict__ W1, const float* __restrict__ b1)
{
    int b0 = blockIdx.x * GQ;
    int t = threadIdx.x, lane = t & 31, w = t >> 5;
    __shared__ float qin[GQ][INDIM];
    __shared__ float qsm[GQ][LAT];
    __shared__ float wk_sm[16][INDIM];
    __shared__ int sidx[GQ];

    if (t < GQ) sidx[t] = tidx[b0 + t];
    __syncthreads();

    for (int m = t; m < GQ * 96; m += 512) {
        int q = m / 96, c4 = m % 96;
        float4 v;
        if (c4 < 32)      v = ((const float4*)(x    + (size_t)sidx[q] * LAT))[c4];
        else if (c4 < 64) v = ((const float4*)(mem  + (size_t)sidx[q] * LAT))[c4 - 32];
        else              v = ((const float4*)(tart + (size_t)(b0 + q) * LAT))[c4 - 64];
        *(float4*)&qin[q][c4 * 4] = v;
    }
    __syncthreads();

    // q = Wq @ qin + bq  (warp-per-output, multi-reduce)
    for (int oi = 0; oi < 8; oi++) {
        int o = w * 8 + oi;
        const float* wr = Wq + (size_t)o * INDIM;
        float wreg[12];
        #pragma unroll
        for (int r = 0; r < 12; r++) wreg[r] = wr[lane + 32 * r];
        float p[GQ];
        #pragma unroll
        for (int q = 0; q < GQ; q++) {
            float s = 0.f;
            #pragma unroll
            for (int r = 0; r < 12; r++) s = fmaf(wreg[r], qin[q][lane + 32 * r], s);
            p[q] = s;
        }
        float a0 = mrg(p[0], p[1], 16, lane), a1 = mrg(p[2], p[3], 16, lane);
        float a2 = mrg(p[4], p[5], 16, lane), a3 = mrg(p[6], p[7], 16, lane);
        float b4 = mrg(a0, a1, 8, lane), b5 = mrg(a2, a3, 8, lane);
        float c0 = mrg(b4, b5, 4, lane);
        c0 += __shfl_xor_sync(0xffffffffu, c0, 1);
        c0 += __shfl_xor_sync(0xffffffffu, c0, 2);
        float bias = bq[o];
        if ((lane & 3) == 0) {
            int q = ((lane >> 4) & 1) + ((lane >> 2) & 2) + (lane & 4);
            qsm[q][o] = c0 + bias;
        }
    }

    // hpart = W1b @ qin + b1  (W1 columns 128..511 multiply q_input)
    for (int oi = 0; oi < 8; oi++) {
        int o = w * 8 + oi;
        const float* wr = W1 + (size_t)o * FFNIN + LAT;
        float wreg[12];
        #pragma unroll
        for (int r = 0; r < 12; r++) wreg[r] = wr[lane + 32 * r];
        float p[GQ];
        #pragma unroll
        for (int q = 0; q < GQ; q++) {
            float s = 0.f;
            #pragma unroll
            for (int r = 0; r < 12; r++) s = fmaf(wreg[r], qin[q][lane + 32 * r], s);
            p[q] = s;
        }
        float a0 = mrg(p[0], p[1], 16, lane), a1 = mrg(p[2], p[3], 16, lane);
        float a2 = mrg(p[4], p[5], 16, lane), a3 = mrg(p[6], p[7], 16, lane);
        float b4 = mrg(a0, a1, 8, lane), b5 = mrg(a2, a3, 8, lane);
        float c0 = mrg(b4, b5, 4, lane);
        c0 += __shfl_xor_sync(0xffffffffu, c0, 1);
        c0 += __shfl_xor_sync(0xffffffffu, c0, 2);
        float bias = b1[o];
        if ((lane & 3) == 0) {
            int q = ((lane >> 4) & 1) + ((lane >> 2) & 2) + (lane & 4);
            g_hpart[(size_t)(b0 + q) * LAT + o] = c0 + bias;
        }
    }
    __syncthreads();

    // qbias[q] = q . bk
    if (w < GQ) {
        float v = 0.f;
        #pragma unroll
        for (int r = 0; r < 4; r++) v = fmaf(qsm[w][lane + 32 * r], bk[lane + 32 * r], v);
        #pragma unroll
        for (int off = 16; off; off >>= 1) v += __shfl_xor_sync(0xffffffffu, v, off);
        if (lane == 0) g_qbias[b0 + w] = v;
    }

    // qk = Wk^T q  (smem-staged Wk tiles)
    float acc[GQ];
    #pragma unroll
    for (int q = 0; q < GQ; q++) acc[q] = 0.f;
    for (int j0 = 0; j0 < LAT; j0 += 16) {
        __syncthreads();
        for (int m = t; m < 16 * 96; m += 512) {
            int jj = m / 96, c4 = m % 96;
            *(float4*)&wk_sm[jj][c4 * 4] =
                ((const float4*)(Wk + (size_t)(j0 + jj) * INDIM))[c4];
        }
        __syncthreads();
        if (t < INDIM) {
            #pragma unroll
            for (int jj = 0; jj < 16; jj++) {
                float wv = wk_sm[jj][t];
                #pragma unroll
                for (int q = 0; q < GQ; q++) acc[q] = fmaf(qsm[q][j0 + jj], wv, acc[q]);
            }
        }
    }
    if (t < INDIM) {
        #pragma unroll
        for (int q = 0; q < GQ; q++) g_qk[(size_t)(b0 + q) * INDIM + t] = acc[q];
    }
}

// ---------------------------------------------------------------------------
// Kernel 2: mask scan -> edge lists. 1024 blocks x 256 thr (R5-proven).
// Mask is 4-byte elements (traffic-proven, R3/R5): word != 0 <=> edge.
// ---------------------------------------------------------------------------
#define PROC4(u, base) \
    if (u.x | u.y | u.z | u.w) { \
        if (u.x) { int sl = atomicAdd(&s_cnt, 1); if (sl < CAP) s_idx[sl] = (base) * 4 + 0; } \
        if (u.y) { int sl = atomicAdd(&s_cnt, 1); if (sl < CAP) s_idx[sl] = (base) * 4 + 1; } \
        if (u.z) { int sl = atomicAdd(&s_cnt, 1); if (sl < CAP) s_idx[sl] = (base) * 4 + 2; } \
        if (u.w) { int sl = atomicAdd(&s_cnt, 1); if (sl < CAP) s_idx[sl] = (base) * 4 + 3; } }

__global__ void __launch_bounds__(256) k_scan(
    const unsigned char* __restrict__ maskb, const int* __restrict__ tidx)
{
    int b = blockIdx.x, t = threadIdx.x;
    __shared__ int s_idx[CAP];
    __shared__ int s_cnt;
    if (t == 0) s_cnt = 0;
    __syncthreads();

    const uint4* row = (const uint4*)(maskb + (size_t)b * NN * 4);
    const int NW = NN / 4;                    // 25000 uint4
    int i = t;
    for (; i + 768 < NW; i += 1024) {
        uint4 a = row[i], b4 = row[i + 256], c4 = row[i + 512], d4 = row[i + 768];
        PROC4(a, i) PROC4(b4, i + 256) PROC4(c4, i + 512) PROC4(d4, i + 768)
    }
    for (; i < NW; i += 256) { uint4 u = row[i]; PROC4(u, i) }

    __syncthreads();
    int cnt = min(s_cnt, CAP);
    if (cnt == 0) {
        if (t == 0) { g_list[b * CAP] = tidx[b]; g_cnt[b] = 1; }
        return;
    }
    for (int m = t; m < cnt; m += 256) g_list[b * CAP + m] = s_idx[m];
    if (t == 0) g_cnt[b] = cnt;
}

// ---------------------------------------------------------------------------
// Kernel 3: pipelined online-softmax gather. 1024 blocks x 512 thr (R5-proven).
// ---------------------------------------------------------------------------
__global__ void __launch_bounds__(512) k_gather(
    const float* __restrict__ x, const float* __restrict__ mem,
    const float* __restrict__ dt)
{
    int b = blockIdx.x, t = threadIdx.x, lane = t & 31, w = t >> 5;
    __shared__ float s_qk[INDIM];
    __shared__ float s_part[16][INDIM];
    __shared__ float s_m[16], s_l[16];

    if (t < INDIM) s_qk[t] = g_qk[(size_t)b * INDIM + t];
    __syncthreads();
    int cnt = g_cnt[b];
    float qb = g_qbias[b];
    const float scale = 0.08838834764831845f;   // 1/sqrt(128)

    float m = -INFINITY, l = 0.f;
    float racc[12];
    #pragma unroll
    for (int r = 0; r < 12; r++) racc[r] = 0.f;

    int p = w;
    float rowv[12];
    if (p < cnt) {
        int n = g_list[b * CAP + p];
        const float* px = x + (size_t)n * LAT;
        const float* pm = mem + (size_t)n * LAT;
        const float* pd = dt + (size_t)n * LAT;
        #pragma unroll
        for (int r = 0; r < 4; r++) rowv[r]     = px[lane + 32 * r];
        #pragma unroll
        for (int r = 0; r < 4; r++) rowv[4 + r] = pm[lane + 32 * r];
        #pragma unroll
        for (int r = 0; r < 4; r++) rowv[8 + r] = pd[lane + 32 * r];
    }
    while (p < cnt) {
        int pn = p + 16;
        float rnext[12];
        if (pn < cnt) {
            int n = g_list[b * CAP + pn];
            const float* px = x + (size_t)n * LAT;
            const float* pm = mem + (size_t)n * LAT;
            const float* pd = dt + (size_t)n * LAT;
            #pragma unroll
            for (int r = 0; r < 4; r++) rnext[r]     = px[lane + 32 * r];
            #pragma unroll
            for (int r = 0; r < 4; r++) rnext[4 + r] = pm[lane + 32 * r];
            #pragma unroll
            for (int r = 0; r < 4; r++) rnext[8 + r] = pd[lane + 32 * r];
        }
        float dot = 0.f;
        #pragma unroll
        for (int r = 0; r < 12; r++) dot = fmaf(rowv[r], s_qk[32 * r + lane], dot);
        #pragma unroll
        for (int off = 16; off; off >>= 1) dot += __shfl_xor_sync(0xffffffffu, dot, off);
        float s = (dot + qb) * scale;
        float mnew = fmaxf(m, s);
        float corr = __expf(m - mnew);
        float e = __expf(s - mnew);
        l = l * corr + e;
        m = mnew;
        #pragma unroll
        for (int r = 0; r < 12; r++) racc[r] = fmaf(racc[r], corr, e * rowv[r]);
        #pragma unroll
        for (int r = 0; r < 12; r++) rowv[r] = rnext[r];
        p = pn;
    }
    #pragma unroll
    for (int r = 0; r < 12; r++) s_part[w][32 * r + lane] = racc[r];
    if (lane == 0) { s_m[w] = m; s_l[w] = l; }
    __syncthreads();

    float M = s_m[0];
    #pragma unroll
    for (int i = 1; i < 16; i++) M = fmaxf(M, s_m[i]);
    float L = 0.f;
    float ef[16];
    #pragma unroll
    for (int i = 0; i < 16; i++) { ef[i] = __expf(s_m[i] - M); L += s_l[i] * ef[i]; }
    float invL = 1.f / L;
    if (t < INDIM) {
        float sum = 0.f;
        #pragma unroll
        for (int i = 0; i < 16; i++) sum = fmaf(s_part[i][t], ef[i], sum);
        g_acc[(size_t)b * INDIM + t] = sum * invL;
    }
}

// ---------------------------------------------------------------------------
// Kernel 4: folded epilogue — only 2 GEMV stages.
//   h = relu(Wfold @ acc + hpart + cvec) ; out = W2 @ h + b2
// 128 blocks x 512 threads, GQ=8.
// ---------------------------------------------------------------------------
__global__ void __launch_bounds__(512) k_epi(
    const float* __restrict__ W2, const float* __restrict__ b2,
    float* __restrict__ out)
{
    int b0 = blockIdx.x * GQ;
    int t = threadIdx.x, lane = t & 31, w = t >> 5;
    __shared__ float acc[GQ][INDIM];
    __shared__ float hp[GQ][LAT];
    __shared__ float h[GQ][LAT];

    for (int m = t; m < GQ * 96; m += 512) {
        int q = m / 96, c4 = m % 96;
        *(float4*)&acc[q][c4 * 4] = *(const float4*)&g_acc[(size_t)(b0 + q) * INDIM + c4 * 4];
    }
    for (int m = t; m < GQ * LAT; m += 512) {
        int q = m >> 7, o = m & 127;
        hp[q][o] = g_hpart[(size_t)(b0 + q) * LAT + o] + g_cvec[o];
    }
    __syncthreads();

    // stage 1: h = relu(Wfold @ acc + hp)
    for (int oi = 0; oi < 8; oi++) {
        int o = w * 8 + oi;
        const float* wr = g_Wfold + (size_t)o * INDIM;
        float wreg[12];
        #pragma unroll
        for (int r = 0; r < 12; r++) wreg[r] = wr[lane + 32 * r];
        float p[GQ];
        #pragma unroll
        for (int q = 0; q < GQ; q++) {
            float s = 0.f;
            #pragma unroll
            for (int r = 0; r < 12; r++) s = fmaf(wreg[r], acc[q][lane + 32 * r], s);
            p[q] = s;
        }
        float a0 = mrg(p[0], p[1], 16, lane), a1 = mrg(p[2], p[3], 16, lane);
        float a2 = mrg(p[4], p[5], 16, lane), a3 = mrg(p[6], p[7], 16, lane);
        float b4 = mrg(a0, a1, 8, lane), b5 = mrg(a2, a3, 8, lane);
        float c0 = mrg(b4, b5, 4, lane);
        c0 += __shfl_xor_sync(0xffffffffu, c0, 1);
        c0 += __shfl_xor_sync(0xffffffffu, c0, 2);
        if ((lane & 3) == 0) {
            int q = ((lane >> 4) & 1) + ((lane >> 2) & 2) + (lane & 4);
            h[q][o] = fmaxf(c0 + hp[q][o], 0.f);
        }
    }
    __syncthreads();

    // stage 2: out = W2 @ h + b2
    for (int oi = 0; oi < 8; oi++) {
        int o = w * 8 + oi;
        const float* wr = W2 + (size_t)o * LAT;
        float wreg[4];
        #pragma unroll
        for (int r = 0; r < 4; r++) wreg[r] = wr[lane + 32 * r];
        float p[GQ];
        #pragma unroll
        for (int q = 0; q < GQ; q++) {
            float s = 0.f;
            #pragma unroll
            for (int r = 0; r < 4; r++) s = fmaf(wreg[r], h[q][lane + 32 * r], s);
            p[q] = s;
        }
        float a0 = mrg(p[0], p[1], 16, lane), a1 = mrg(p[2], p[3], 16, lane);
        float a2 = mrg(p[4], p[5], 16, lane), a3 = mrg(p[6], p[7], 16, lane);
        float b4 = mrg(a0, a1, 8, lane), b5 = mrg(a2, a3, 8, lane);
        float c0 = mrg(b4, b5, 4, lane);
        c0 += __shfl_xor_sync(0xffffffffu, c0, 1);
        c0 += __shfl_xor_sync(0xffffffffu, c0, 2);
        float bias = b2[o];
        if ((lane & 3) == 0) {
            int q = ((lane >> 4) & 1) + ((lane >> 2) & 2) + (lane & 4);
            out[(size_t)(b0 + q) * LAT + o] = c0 + bias;
        }
    }
}

// ---------------------------------------------------------------------------
extern "C" void kernel_launch(void* const* d_in, const int* in_sizes, int n_in,
                              void* d_out, int out_size)
{
    const float* x    = (const float*)d_in[0];
    const float* mem  = (const float*)d_in[1];
    const float* dt   = (const float*)d_in[2];
    const float* tart = (const float*)d_in[3];
    const unsigned char* mask = (const unsigned char*)d_in[4];
    const int*   tidx = (const int*)d_in[5];
    const float* Wq = (const float*)d_in[6];
    const float* bq = (const float*)d_in[7];
    const float* Wk = (const float*)d_in[8];
    const float* bk = (const float*)d_in[9];
    const float* Wv = (const float*)d_in[10];
    const float* bv = (const float*)d_in[11];
    const float* W1 = (const float*)d_in[12];
    const float* b1 = (const float*)d_in[13];
    const float* W2 = (const float*)d_in[14];
    const float* b2 = (const float*)d_in[15];
    float* out = (float*)d_out;

    // Fork-join: fold+prep (weights path) run concurrently with scan (mask path).
    static cudaStream_t s_side = nullptr;
    static cudaEvent_t e_fork = nullptr, e_join = nullptr;
    if (s_side == nullptr) {
        cudaStreamCreateWithFlags(&s_side, cudaStreamNonBlocking);
        cudaEventCreateWithFlags(&e_fork, cudaEventDisableTiming);
        cudaEventCreateWithFlags(&e_join, cudaEventDisableTiming);
    }

    cudaEventRecord(e_fork, 0);
    cudaStreamWaitEvent(s_side, e_fork, 0);
    k_fold<<<LAT, 384, 0, s_side>>>(W1, Wv, bv);
    k_prep<<<BB / GQ, 512, 0, s_side>>>(x, mem, tart, tidx, Wq, bq, Wk, bk, W1, b1);
    cudaEventRecord(e_join, s_side);

    k_scan<<<BB, 256>>>(mask, tidx);

    cudaStreamWaitEvent(0, e_join, 0);
    k_gather<<<BB, 512>>>(x, mem, dt);
    k_epi<<<BB / GQ, 512>>>(W2, b2, out);
}

// round 8
// speedup vs baseline: 1.1815x; 1.0112x over previous
#include <cuda_runtime.h>
#include <math.h>

// Problem constants (fixed shapes per reference)
#define NN 100000
#define BB 1024
#define LAT 128
#define INDIM 384      // NODE_DIM + 2*LATENT
#define FFNIN 512      // LATENT + IN_DIM
#define CAP 512        // neighbor list capacity (mean ~50)
#define GQ 8           // queries per block in prep

// Scratch (device globals; no allocation allowed)
__device__ float g_qk[BB * INDIM];
__device__ float g_hpart[BB * LAT];     // W1b @ q_input + b1 + W1a @ bv
__device__ float g_Wfold[LAT * INDIM];  // W1a @ Wv
__device__ int   g_list[BB * CAP];
__device__ int   g_cnt[BB];

// Merge two partial-sum arrays across xor-lane distance `bit`
__device__ __forceinline__ float mrg(float a, float b, int bit, int lane) {
    float keep = (lane & bit) ? b : a;
    float send = (lane & bit) ? a : b;
    return keep + __shfl_xor_sync(0xffffffffu, send, bit);
}

// ---------------------------------------------------------------------------
// Kernel 1 (side stream): prep + fold. 128 blocks x 512 threads.
//   Per block: GQ=8 queries:
//     qin = [x[idx], mem[idx], tar_t]; q = Wq@qin + bq; qk = Wk^T q
//     hpart = W1b@qin + b1 + cvec   (cvec = W1a@bv, row o = blockIdx)
//   Plus one Wfold row: Wfold[o] = W1a[o] @ Wv   (o = blockIdx)
//   NOTE: q.bk (qbias) is dropped — constant per query, cancels in softmax.
// ---------------------------------------------------------------------------
__global__ void __launch_bounds__(512) k_prep(
    const float* __restrict__ x, const float* __restrict__ mem,
    const float* __restrict__ tart, const int* __restrict__ tidx,
    const float* __restrict__ Wq, const float* __restrict__ bq,
    const float* __restrict__ Wk, const float* __restrict__ W1,
    const float* __restrict__ b1, const float* __restrict__ Wv,
    const float* __restrict__ bv)
{
    int b0 = blockIdx.x * GQ;
    int t = threadIdx.x, lane = t & 31, w = t >> 5;
    __shared__ float qin[GQ][INDIM];
    __shared__ float qsm[GQ][LAT];
    __shared__ float wk_sm[16][INDIM];
    __shared__ float w1a[LAT];
    __shared__ float red[4];
    __shared__ float s_cvec;
    __shared__ int sidx[GQ];

    if (t < GQ) sidx[t] = tidx[b0 + t];
    // fold row for o = blockIdx.x
    if (t < LAT) w1a[t] = W1[(size_t)blockIdx.x * FFNIN + t];
    __syncthreads();

    // ---- Wfold row: Wfold[o][c] = sum_j w1a[j] * Wv[j][c] ----
    if (t < INDIM) {
        float s = 0.f;
        #pragma unroll 8
        for (int j = 0; j < LAT; j++) s = fmaf(w1a[j], Wv[(size_t)j * INDIM + t], s);
        g_Wfold[(size_t)blockIdx.x * INDIM + t] = s;
    }
    // cvec[o] = w1a . bv  (one scalar per block)
    if (w == 15) {
        float v = 0.f;
        #pragma unroll
        for (int r = 0; r < 4; r++) v = fmaf(w1a[lane + 32 * r], bv[lane + 32 * r], v);
        #pragma unroll
        for (int off = 16; off; off >>= 1) v += __shfl_xor_sync(0xffffffffu, v, off);
        if (lane == 0) s_cvec = v;
    }

    // ---- gather q_input ----
    for (int m = t; m < GQ * 96; m += 512) {
        int q = m / 96, c4 = m % 96;
        float4 v;
        if (c4 < 32)      v = ((const float4*)(x    + (size_t)sidx[q] * LAT))[c4];
        else if (c4 < 64) v = ((const float4*)(mem  + (size_t)sidx[q] * LAT))[c4 - 32];
        else              v = ((const float4*)(tart + (size_t)(b0 + q) * LAT))[c4 - 64];
        *(float4*)&qin[q][c4 * 4] = v;
    }
    __syncthreads();

    // ---- q = Wq @ qin + bq  (warp-per-output, multi-reduce) ----
    for (int oi = 0; oi < 8; oi++) {
        int o = w * 8 + oi;
        const float* wr = Wq + (size_t)o * INDIM;
        float wreg[12];
        #pragma unroll
        for (int r = 0; r < 12; r++) wreg[r] = wr[lane + 32 * r];
        float p[GQ];
        #pragma unroll
        for (int q = 0; q < GQ; q++) {
            float s = 0.f;
            #pragma unroll
            for (int r = 0; r < 12; r++) s = fmaf(wreg[r], qin[q][lane + 32 * r], s);
            p[q] = s;
        }
        float a0 = mrg(p[0], p[1], 16, lane), a1 = mrg(p[2], p[3], 16, lane);
        float a2 = mrg(p[4], p[5], 16, lane), a3 = mrg(p[6], p[7], 16, lane);
        float b4 = mrg(a0, a1, 8, lane), b5 = mrg(a2, a3, 8, lane);
        float c0 = mrg(b4, b5, 4, lane);
        c0 += __shfl_xor_sync(0xffffffffu, c0, 1);
        c0 += __shfl_xor_sync(0xffffffffu, c0, 2);
        float bias = bq[o];
        if ((lane & 3) == 0) {
            int q = ((lane >> 4) & 1) + ((lane >> 2) & 2) + (lane & 4);
            qsm[q][o] = c0 + bias;
        }
    }

    // ---- hpart = W1b @ qin + b1 + cvec ----
    for (int oi = 0; oi < 8; oi++) {
        int o = w * 8 + oi;
        const float* wr = W1 + (size_t)o * FFNIN + LAT;
        float wreg[12];
        #pragma unroll
        for (int r = 0; r < 12; r++) wreg[r] = wr[lane + 32 * r];
        float p[GQ];
        #pragma unroll
        for (int q = 0; q < GQ; q++) {
            float s = 0.f;
            #pragma unroll
            for (int r = 0; r < 12; r++) s = fmaf(wreg[r], qin[q][lane + 32 * r], s);
            p[q] = s;
        }
        float a0 = mrg(p[0], p[1], 16, lane), a1 = mrg(p[2], p[3], 16, lane);
        float a2 = mrg(p[4], p[5], 16, lane), a3 = mrg(p[6], p[7], 16, lane);
        float b4 = mrg(a0, a1, 8, lane), b5 = mrg(a2, a3, 8, lane);
        float c0 = mrg(b4, b5, 4, lane);
        c0 += __shfl_xor_sync(0xffffffffu, c0, 1);
        c0 += __shfl_xor_sync(0xffffffffu, c0, 2);
        float bias = b1[o];
        if ((lane & 3) == 0) {
            int q = ((lane >> 4) & 1) + ((lane >> 2) & 2) + (lane & 4);
            g_hpart[(size_t)(b0 + q) * LAT + o] = c0 + bias;   // cvec added in gather
        }
    }
    __syncthreads();

    // ---- qk = Wk^T q  (smem-staged Wk tiles) ----
    float acc[GQ];
    #pragma unroll
    for (int q = 0; q < GQ; q++) acc[q] = 0.f;
    for (int j0 = 0; j0 < LAT; j0 += 16) {
        __syncthreads();
        for (int m = t; m < 16 * 96; m += 512) {
            int jj = m / 96, c4 = m % 96;
            *(float4*)&wk_sm[jj][c4 * 4] =
                ((const float4*)(Wk + (size_t)(j0 + jj) * INDIM))[c4];
        }
        __syncthreads();
        if (t < INDIM) {
            #pragma unroll
            for (int jj = 0; jj < 16; jj++) {
                float wv = wk_sm[jj][t];
                #pragma unroll
                for (int q = 0; q < GQ; q++) acc[q] = fmaf(qsm[q][j0 + jj], wv, acc[q]);
            }
        }
    }
    if (t < INDIM) {
        #pragma unroll
        for (int q = 0; q < GQ; q++) g_qk[(size_t)(b0 + q) * INDIM + t] = acc[q];
    }
    // write cvec into a dedicated slot appended to g_Wfold? No — fold cvec into
    // g_hpart is impossible here (hpart rows belong to other blocks' o). Store
    // per-o cvec via g_hpart is wrong; use separate array:
    // (declared below, written by thread 0)
    extern __device__ float g_cvec[];
    if (t == 0) g_cvec[blockIdx.x] = s_cvec;
}

__device__ float g_cvec[LAT];           // W1a @ bv

// ---------------------------------------------------------------------------
// Kernel 2: mask scan -> edge lists. 1024 blocks x 256 thr (proven config).
// Mask is 4-byte elements (traffic-proven): word != 0 <=> edge.
// ---------------------------------------------------------------------------
#define PROC4(u, base) \
    if (u.x | u.y | u.z | u.w) { \
        if (u.x) { int sl = atomicAdd(&s_cnt, 1); if (sl < CAP) s_idx[sl] = (base) * 4 + 0; } \
        if (u.y) { int sl = atomicAdd(&s_cnt, 1); if (sl < CAP) s_idx[sl] = (base) * 4 + 1; } \
        if (u.z) { int sl = atomicAdd(&s_cnt, 1); if (sl < CAP) s_idx[sl] = (base) * 4 + 2; } \
        if (u.w) { int sl = atomicAdd(&s_cnt, 1); if (sl < CAP) s_idx[sl] = (base) * 4 + 3; } }

__global__ void __launch_bounds__(256) k_scan(
    const unsigned char* __restrict__ maskb, const int* __restrict__ tidx)
{
    int b = blockIdx.x, t = threadIdx.x;
    __shared__ int s_idx[CAP];
    __shared__ int s_cnt;
    if (t == 0) s_cnt = 0;
    __syncthreads();

    const uint4* row = (const uint4*)(maskb + (size_t)b * NN * 4);
    const int NW = NN / 4;                    // 25000 uint4
    int i = t;
    for (; i + 768 < NW; i += 1024) {
        uint4 a = row[i], b4 = row[i + 256], c4 = row[i + 512], d4 = row[i + 768];
        PROC4(a, i) PROC4(b4, i + 256) PROC4(c4, i + 512) PROC4(d4, i + 768)
    }
    for (; i < NW; i += 256) { uint4 u = row[i]; PROC4(u, i) }

    __syncthreads();
    int cnt = min(s_cnt, CAP);
    if (cnt == 0) {
        if (t == 0) { g_list[b * CAP] = tidx[b]; g_cnt[b] = 1; }
        return;
    }
    for (int m = t; m < cnt; m += 256) g_list[b * CAP + m] = s_idx[m];
    if (t == 0) g_cnt[b] = cnt;
}

// ---------------------------------------------------------------------------
// Kernel 3: gather + online softmax + FOLDED FFN epilogue, all in one block.
// 1024 blocks x 512 thr. Writes final output directly.
// ---------------------------------------------------------------------------
__global__ void __launch_bounds__(512, 2) k_gather(
    const float* __restrict__ x, const float* __restrict__ mem,
    const float* __restrict__ dt, const float* __restrict__ W2,
    const float* __restrict__ b2, float* __restrict__ out)
{
    int b = blockIdx.x, t = threadIdx.x, lane = t & 31, w = t >> 5;
    __shared__ float s_qk[INDIM];
    __shared__ float s_part[16][INDIM];
    __shared__ float s_m[16], s_l[16];
    __shared__ float s_acc[INDIM];
    __shared__ float s_hp[LAT];
    __shared__ float s_h[LAT];

    if (t < INDIM) s_qk[t] = g_qk[(size_t)b * INDIM + t];
    if (t >= INDIM && t < INDIM + LAT) {
        int o = t - INDIM;
        s_hp[o] = g_hpart[(size_t)b * LAT + o] + g_cvec[o];
    }
    __syncthreads();
    int cnt = g_cnt[b];
    const float scale = 0.08838834764831845f;   // 1/sqrt(128)

    float m = -INFINITY, l = 0.f;
    float racc[12];
    #pragma unroll
    for (int r = 0; r < 12; r++) racc[r] = 0.f;

    int p = w;
    float rowv[12];
    if (p < cnt) {
        int n = g_list[b * CAP + p];
        const float* px = x + (size_t)n * LAT;
        const float* pm = mem + (size_t)n * LAT;
        const float* pd = dt + (size_t)n * LAT;
        #pragma unroll
        for (int r = 0; r < 4; r++) rowv[r]     = px[lane + 32 * r];
        #pragma unroll
        for (int r = 0; r < 4; r++) rowv[4 + r] = pm[lane + 32 * r];
        #pragma unroll
        for (int r = 0; r < 4; r++) rowv[8 + r] = pd[lane + 32 * r];
    }
    while (p < cnt) {
        int pn = p + 16;
        float rnext[12];
        if (pn < cnt) {
            int n = g_list[b * CAP + pn];
            const float* px = x + (size_t)n * LAT;
            const float* pm = mem + (size_t)n * LAT;
            const float* pd = dt + (size_t)n * LAT;
            #pragma unroll
            for (int r = 0; r < 4; r++) rnext[r]     = px[lane + 32 * r];
            #pragma unroll
            for (int r = 0; r < 4; r++) rnext[4 + r] = pm[lane + 32 * r];
            #pragma unroll
            for (int r = 0; r < 4; r++) rnext[8 + r] = pd[lane + 32 * r];
        }
        float dot = 0.f;
        #pragma unroll
        for (int r = 0; r < 12; r++) dot = fmaf(rowv[r], s_qk[32 * r + lane], dot);
        #pragma unroll
        for (int off = 16; off; off >>= 1) dot += __shfl_xor_sync(0xffffffffu, dot, off);
        float s = dot * scale;                  // qbias dropped: softmax shift-invariant
        float mnew = fmaxf(m, s);
        float corr = __expf(m - mnew);
        float e = __expf(s - mnew);
        l = l * corr + e;
        m = mnew;
        #pragma unroll
        for (int r = 0; r < 12; r++) racc[r] = fmaf(racc[r], corr, e * rowv[r]);
        #pragma unroll
        for (int r = 0; r < 12; r++) rowv[r] = rnext[r];
        p = pn;
    }
    #pragma unroll
    for (int r = 0; r < 12; r++) s_part[w][32 * r + lane] = racc[r];
    if (lane == 0) { s_m[w] = m; s_l[w] = l; }
    __syncthreads();

    // merge 16 warp-local online-softmax states -> s_acc
    {
        float M = s_m[0];
        #pragma unroll
        for (int i = 1; i < 16; i++) M = fmaxf(M, s_m[i]);
        float L = 0.f;
        float ef[16];
        #pragma unroll
        for (int i = 0; i < 16; i++) { ef[i] = __expf(s_m[i] - M); L += s_l[i] * ef[i]; }
        float invL = 1.f / L;
        if (t < INDIM) {
            float sum = 0.f;
            #pragma unroll
            for (int i = 0; i < 16; i++) sum = fmaf(s_part[i][t], ef[i], sum);
            s_acc[t] = sum * invL;
        }
    }
    __syncthreads();

    // ---- FFN stage 1: h = relu(Wfold @ acc + hpart) ----
    for (int oi = 0; oi < 8; oi++) {
        int o = w * 8 + oi;
        const float* wr = g_Wfold + (size_t)o * INDIM;
        float dot = 0.f;
        #pragma unroll
        for (int r = 0; r < 12; r++) dot = fmaf(wr[lane + 32 * r], s_acc[lane + 32 * r], dot);
        #pragma unroll
        for (int off = 16; off; off >>= 1) dot += __shfl_xor_sync(0xffffffffu, dot, off);
        if (lane == 0) s_h[o] = fmaxf(dot + s_hp[o], 0.f);
    }
    __syncthreads();

    // ---- FFN stage 2: out = W2 @ h + b2 ----
    for (int oi = 0; oi < 8; oi++) {
        int o = w * 8 + oi;
        const float* wr = W2 + (size_t)o * LAT;
        float dot = 0.f;
        #pragma unroll
        for (int r = 0; r < 4; r++) dot = fmaf(wr[lane + 32 * r], s_h[lane + 32 * r], dot);
        #pragma unroll
        for (int off = 16; off; off >>= 1) dot += __shfl_xor_sync(0xffffffffu, dot, off);
        if (lane == 0) out[(size_t)b * LAT + o] = dot + b2[o];
    }
}

// ---------------------------------------------------------------------------
extern "C" void kernel_launch(void* const* d_in, const int* in_sizes, int n_in,
                              void* d_out, int out_size)
{
    const float* x    = (const float*)d_in[0];
    const float* mem  = (const float*)d_in[1];
    const float* dt   = (const float*)d_in[2];
    const float* tart = (const float*)d_in[3];
    const unsigned char* mask = (const unsigned char*)d_in[4];
    const int*   tidx = (const int*)d_in[5];
    const float* Wq = (const float*)d_in[6];
    const float* bq = (const float*)d_in[7];
    const float* Wk = (const float*)d_in[8];
    // bk (d_in[9]) unused: q.bk cancels in softmax
    const float* Wv = (const float*)d_in[10];
    const float* bv = (const float*)d_in[11];
    const float* W1 = (const float*)d_in[12];
    const float* b1 = (const float*)d_in[13];
    const float* W2 = (const float*)d_in[14];
    const float* b2 = (const float*)d_in[15];
    float* out = (float*)d_out;

    // Fork-join: prep+fold (weights path) concurrent with scan (mask path).
    static cudaStream_t s_side = nullptr;
    static cudaEvent_t e_fork = nullptr, e_join = nullptr;
    if (s_side == nullptr) {
        cudaStreamCreateWithFlags(&s_side, cudaStreamNonBlocking);
        cudaEventCreateWithFlags(&e_fork, cudaEventDisableTiming);
        cudaEventCreateWithFlags(&e_join, cudaEventDisableTiming);
    }

    cudaEventRecord(e_fork, 0);
    cudaStreamWaitEvent(s_side, e_fork, 0);
    k_prep<<<BB / GQ, 512, 0, s_side>>>(x, mem, tart, tidx, Wq, bq, Wk, W1, b1, Wv, bv);
    cudaEventRecord(e_join, s_side);

    k_scan<<<BB, 256>>>(mask, tidx);

    cudaStreamWaitEvent(0, e_join, 0);
    k_gather<<<BB, 512>>>(x, mem, dt, W2, b2, out);
}